// round 1
// baseline (speedup 1.0000x reference)
#include <cuda_runtime.h>
#include <cstdint>
#include <cstddef>

#define B_ 16
#define C_ 64
#define T_ 400
#define F_ 64
#define H_ 64
#define G_ 8
#define N1 (B_*T_)       // 6400 intra sequences
#define NQ 1024          // PE sequences total (G * 128)
#define GATE3 192

// ---------------- scratch (static __device__, no allocation) ----------------
__device__ float g_gx1[(size_t)2*N1*F_*GATE3];   // [dir][n][p][192]
__device__ float g_fb [(size_t)N1*F_*128];       // [n][f][fwd64|bwd64]
__device__ float g_intra[(size_t)N1*F_*C_];      // [n=b*T+t][f][c]  (LN'd intra, pre-residual)
__device__ float g_pein[(size_t)B_*F_*T_*C_];    // [b][f][t][c]     (intra_out = xp + intra)
__device__ float g_gx2[(size_t)NQ*T_*GATE3];     // [q][t][192]
__device__ float g_rnn[(size_t)B_*T_*F_*H_];     // [b][t][f][h]

// ---------------- helpers ----------------
__device__ __forceinline__ float fsigm(float x) {
    return __fdividef(1.0f, 1.0f + __expf(-x));
}
__device__ __forceinline__ float ftanh(float x) {
    x = fminf(15.0f, fmaxf(-15.0f, x));
    float e = __expf(2.0f * x);
    return __fdividef(e - 1.0f, e + 1.0f);
}
__device__ __forceinline__ float dot4(float4 a, float4 b) {
    return fmaf(a.x, b.x, fmaf(a.y, b.y, fmaf(a.z, b.z, a.w * b.w)));
}

// block-wide mean / rsqrt(var) over 4096 values; each thread contributes s1,s2
__device__ __forceinline__ void block_stats(float s1, float s2, float* red, int tid,
                                            float& mu, float& rs) {
#pragma unroll
    for (int o = 16; o; o >>= 1) {
        s1 += __shfl_xor_sync(0xffffffffu, s1, o);
        s2 += __shfl_xor_sync(0xffffffffu, s2, o);
    }
    if ((tid & 31) == 0) { red[tid >> 5] = s1; red[8 + (tid >> 5)] = s2; }
    __syncthreads();
    float a = 0.f, b = 0.f;
#pragma unroll
    for (int w = 0; w < 8; w++) { a += red[w]; b += red[8 + w]; }
    mu = a * (1.0f / 4096.0f);
    float var = b * (1.0f / 4096.0f) - mu * mu;
    rs = rsqrtf(var + 1e-8f);
}

// ================= K1: intra gx (both directions) =================
// grid (6400, 2), 256 thr.  out[dir][n][p][g] = xp[n, f(p), :] . Wih[g,:] + bias
// dir==1 reads flipped input (p corresponds to flipped position).
__global__ __launch_bounds__(256) void k_gx_intra(
    const float* __restrict__ x,
    const float* __restrict__ Wf, const float* __restrict__ bihf, const float* __restrict__ bhhf,
    const float* __restrict__ Wb, const float* __restrict__ bihb, const float* __restrict__ bhhb)
{
    extern __shared__ float sm[];
    float* xt = sm;               // [64][65]
    float* Ws = sm + 64 * 65;     // [192][65]
    float* bs = Ws + 192 * 65;    // [192]
    int dir = blockIdx.y;
    int n = blockIdx.x;
    int b = n / T_, t = n - b * T_;
    const float* W   = dir ? Wb   : Wf;
    const float* bih = dir ? bihb : bihf;
    const float* bhh = dir ? bhhb : bhhf;
    int tid = threadIdx.x;

    for (int idx = tid; idx < 4096; idx += 256) {
        int c = idx >> 6, f = idx & 63;
        float v = x[(((size_t)(b * 64 + c)) * T_ + t) * 64 + f];
        int p = dir ? 63 - f : f;
        xt[p * 65 + c] = v;
    }
    for (int idx = tid; idx < 12288; idx += 256) {
        int g = idx >> 6, k = idx & 63;
        Ws[g * 65 + k] = W[idx];
    }
    for (int g = tid; g < 192; g += 256)
        bs[g] = bih[g] + (g < 128 ? bhh[g] : 0.0f);   // fold bhh for r,z gates
    __syncthreads();

    int tf = tid & 15, tg = tid >> 4;
    int p0 = tf * 4, g0 = tg * 12;
    float acc[4][12];
#pragma unroll
    for (int i = 0; i < 4; i++)
#pragma unroll
        for (int j = 0; j < 12; j++) acc[i][j] = 0.f;

#pragma unroll 4
    for (int k = 0; k < 64; k++) {
        float a[4];
#pragma unroll
        for (int i = 0; i < 4; i++) a[i] = xt[(p0 + i) * 65 + k];
#pragma unroll
        for (int j = 0; j < 12; j++) {
            float w = Ws[(g0 + j) * 65 + k];
#pragma unroll
            for (int i = 0; i < 4; i++) acc[i][j] = fmaf(a[i], w, acc[i][j]);
        }
    }
    float* ob = g_gx1 + (((size_t)dir * N1 + n) * 64) * GATE3;
#pragma unroll
    for (int i = 0; i < 4; i++)
#pragma unroll
        for (int j = 0; j < 12; j++)
            ob[(size_t)(p0 + i) * GATE3 + g0 + j] = acc[i][j] + bs[g0 + j];
}

// ================= K2: intra recurrence =================
// grid (400, 2), 256 thr = (64 units j) x (4 k-slices kc). Sb=16 seqs / block.
__global__ __launch_bounds__(256) void k_rec_intra(
    const float* __restrict__ Whf, const float* __restrict__ bhhf,
    const float* __restrict__ Whb, const float* __restrict__ bhhb)
{
    __shared__ float hsh[2][16][64];
    int dir = blockIdx.y;
    const float* Wh  = dir ? Whb  : Whf;
    const float* bhh = dir ? bhhb : bhhf;
    int tid = threadIdx.x;
    int j = tid >> 2, kc = tid & 3;

    const float4* W4 = reinterpret_cast<const float4*>(Wh);
    float4 wr0, wr1, wr2, wr3, wz0, wz1, wz2, wz3, wn0, wn1, wn2, wn3;
    {
        int br = (0 * 64 + j) * 16 + kc * 4;
        int bz = (1 * 64 + j) * 16 + kc * 4;
        int bn_ = (2 * 64 + j) * 16 + kc * 4;
        wr0 = W4[br + 0]; wr1 = W4[br + 1]; wr2 = W4[br + 2]; wr3 = W4[br + 3];
        wz0 = W4[bz + 0]; wz1 = W4[bz + 1]; wz2 = W4[bz + 2]; wz3 = W4[bz + 3];
        wn0 = W4[bn_ + 0]; wn1 = W4[bn_ + 1]; wn2 = W4[bn_ + 2]; wn3 = W4[bn_ + 3];
    }
    float bn = bhh[128 + j];

    for (int i = tid; i < 2 * 16 * 64; i += 256) (&hsh[0][0][0])[i] = 0.f;
    __syncthreads();

    int n0 = blockIdx.x * 16;
    for (int p = 0; p < 64; p++) {
        float (*cur)[64] = hsh[p & 1];
        float (*nxt)[64] = hsh[(p + 1) & 1];
        int forig = dir ? 63 - p : p;
        for (int s = 0; s < 16; s++) {
            const float4* H4 = reinterpret_cast<const float4*>(cur[s]);
            float4 h0 = H4[kc * 4 + 0], h1 = H4[kc * 4 + 1],
                   h2 = H4[kc * 4 + 2], h3 = H4[kc * 4 + 3];
            float pr = (dot4(wr0, h0) + dot4(wr1, h1)) + (dot4(wr2, h2) + dot4(wr3, h3));
            float pz = (dot4(wz0, h0) + dot4(wz1, h1)) + (dot4(wz2, h2) + dot4(wz3, h3));
            float pn = (dot4(wn0, h0) + dot4(wn1, h1)) + (dot4(wn2, h2) + dot4(wn3, h3));
            pr += __shfl_xor_sync(0xffffffffu, pr, 1); pr += __shfl_xor_sync(0xffffffffu, pr, 2);
            pz += __shfl_xor_sync(0xffffffffu, pz, 1); pz += __shfl_xor_sync(0xffffffffu, pz, 2);
            pn += __shfl_xor_sync(0xffffffffu, pn, 1); pn += __shfl_xor_sync(0xffffffffu, pn, 2);

            int n = n0 + s;
            const float* gxb = g_gx1 + (((size_t)dir * N1 + n) * 64 + p) * GATE3;
            float gr = __ldg(gxb + j);
            float gz = __ldg(gxb + 64 + j);
            float gn = __ldg(gxb + 128 + j);
            float hold = cur[s][j];
            float r = fsigm(gr + pr);
            float z = fsigm(gz + pz);
            float nn = ftanh(gn + r * (pn + bn));
            float hnew = nn + z * (hold - nn);
            if (kc == 0) nxt[s][j] = hnew;
            if (kc == 1) g_fb[((size_t)n * 64 + forig) * 128 + dir * 64 + j] = hnew;
        }
        __syncthreads();
    }
}

// ================= K3: intra FC + LN + residual prep =================
// grid (6400), 256 thr.  Per (b,t): Y = cat[fwd,bwd] @ fcW^T + b; LN over (f,c);
// g_intra = LN(Y); g_pein[b][f][t][c] = xp + LN(Y)
__global__ __launch_bounds__(256) void k_fc_ln_intra(
    const float* __restrict__ x,
    const float* __restrict__ fcW, const float* __restrict__ fcb,
    const float* __restrict__ lng, const float* __restrict__ lnb)
{
    extern __shared__ float sm[];
    float* A   = sm;                  // [64][129]
    float* Wsh = A + 64 * 129;        // [64][129]
    float* X   = Wsh + 64 * 129;      // [64][65]
    float* red = X + 64 * 65;         // [16]
    int n = blockIdx.x;
    int b = n / T_, t = n - b * T_;
    int tid = threadIdx.x;

    for (int idx = tid; idx < 64 * 128; idx += 256) {
        int f = idx >> 7, k = idx & 127;
        A[f * 129 + k]   = g_fb[(size_t)n * 8192 + idx];
        Wsh[f * 129 + k] = fcW[idx];
    }
    for (int idx = tid; idx < 4096; idx += 256) {
        int c = idx >> 6, f = idx & 63;
        X[f * 65 + c] = x[(((size_t)(b * 64 + c)) * T_ + t) * 64 + f];
    }
    __syncthreads();

    int tf = tid & 15, to = tid >> 4;
    int f0 = tf * 4, o0 = to * 4;
    float acc[4][4];
#pragma unroll
    for (int i = 0; i < 4; i++)
#pragma unroll
        for (int j = 0; j < 4; j++) acc[i][j] = 0.f;
#pragma unroll 4
    for (int k = 0; k < 128; k++) {
        float a[4], w[4];
#pragma unroll
        for (int i = 0; i < 4; i++) a[i] = A[(f0 + i) * 129 + k];
#pragma unroll
        for (int j = 0; j < 4; j++) w[j] = Wsh[(o0 + j) * 129 + k];
#pragma unroll
        for (int i = 0; i < 4; i++)
#pragma unroll
            for (int j = 0; j < 4; j++) acc[i][j] = fmaf(a[i], w[j], acc[i][j]);
    }
    float s1 = 0.f, s2 = 0.f;
#pragma unroll
    for (int i = 0; i < 4; i++)
#pragma unroll
        for (int j = 0; j < 4; j++) {
            float v = acc[i][j] + fcb[o0 + j];
            acc[i][j] = v;
            s1 += v; s2 += v * v;
        }
    float mu, rs;
    block_stats(s1, s2, red, tid, mu, rs);
#pragma unroll
    for (int i = 0; i < 4; i++) {
        int f = f0 + i;
#pragma unroll
        for (int j = 0; j < 4; j++) {
            int c = o0 + j;
            float yn = (acc[i][j] - mu) * rs * lng[f * 64 + c] + lnb[f * 64 + c];
            g_intra[((size_t)n * 64 + f) * 64 + c] = yn;
            g_pein[(((size_t)(b * 64 + f)) * T_ + t) * 64 + c] = X[f * 65 + c] + yn;
        }
    }
}

// ================= K4: PE gx =================
// grid (1024*10), 256 thr.  40 t-rows per block.
__global__ __launch_bounds__(256) void k_gx_pe(
    const float* __restrict__ peWih, const float* __restrict__ pebih,
    const float* __restrict__ pebhh)
{
    extern __shared__ float sm[];
    float* xt = sm;              // [40][65]
    float* Ws = sm + 40 * 65;    // [192][65]
    float* bs = Ws + 192 * 65;   // [192]
    int bx = blockIdx.x;
    int q = bx / 10, tc = bx - q * 10;
    int t0 = tc * 40;
    int g = q >> 7, nn = q & 127;
    int b = nn >> 3, f = g * 8 + (nn & 7);
    int tid = threadIdx.x;
    const float* W   = peWih + (size_t)g * 12288;
    const float* bih = pebih + g * 192;
    const float* bhh = pebhh + g * 192;

    for (int idx = tid; idx < 2560; idx += 256) {
        int lt = idx >> 6, c = idx & 63;
        xt[lt * 65 + c] = g_pein[(((size_t)(b * 64 + f)) * T_ + t0 + lt) * 64 + c];
    }
    for (int idx = tid; idx < 12288; idx += 256) {
        int gg = idx >> 6, k = idx & 63;
        Ws[gg * 65 + k] = W[idx];
    }
    for (int gg = tid; gg < 192; gg += 256)
        bs[gg] = bih[gg] + (gg < 128 ? bhh[gg] : 0.0f);
    __syncthreads();

    int tf = tid & 7, tg = tid >> 3;
    int r0 = tf * 5, g0 = tg * 6;
    float acc[5][6];
#pragma unroll
    for (int i = 0; i < 5; i++)
#pragma unroll
        for (int j = 0; j < 6; j++) acc[i][j] = 0.f;
#pragma unroll 4
    for (int k = 0; k < 64; k++) {
        float a[5];
#pragma unroll
        for (int i = 0; i < 5; i++) a[i] = xt[(r0 + i) * 65 + k];
#pragma unroll
        for (int j = 0; j < 6; j++) {
            float w = Ws[(g0 + j) * 65 + k];
#pragma unroll
            for (int i = 0; i < 5; i++) acc[i][j] = fmaf(a[i], w, acc[i][j]);
        }
    }
    float* ob = g_gx2 + ((size_t)q * T_ + t0) * GATE3;
#pragma unroll
    for (int i = 0; i < 5; i++)
#pragma unroll
        for (int j = 0; j < 6; j++)
            ob[(size_t)(r0 + i) * GATE3 + g0 + j] = acc[i][j] + bs[g0 + j];
}

// ================= K5: PE recurrence =================
// grid (256), 256 thr. Sb=4 sequences/block, 400 steps.
__global__ __launch_bounds__(256) void k_rec_pe(
    const float* __restrict__ peWhh, const float* __restrict__ pebhh)
{
    __shared__ float hsh[2][4][64];
    int tid = threadIdx.x;
    int j = tid >> 2, kc = tid & 3;
    int q0 = blockIdx.x * 4;
    int g = q0 >> 7;
    const float* Wh = peWhh + (size_t)g * 12288;
    const float4* W4 = reinterpret_cast<const float4*>(Wh);
    float4 wr0, wr1, wr2, wr3, wz0, wz1, wz2, wz3, wn0, wn1, wn2, wn3;
    {
        int br = (0 * 64 + j) * 16 + kc * 4;
        int bz = (1 * 64 + j) * 16 + kc * 4;
        int bn_ = (2 * 64 + j) * 16 + kc * 4;
        wr0 = W4[br + 0]; wr1 = W4[br + 1]; wr2 = W4[br + 2]; wr3 = W4[br + 3];
        wz0 = W4[bz + 0]; wz1 = W4[bz + 1]; wz2 = W4[bz + 2]; wz3 = W4[bz + 3];
        wn0 = W4[bn_ + 0]; wn1 = W4[bn_ + 1]; wn2 = W4[bn_ + 2]; wn3 = W4[bn_ + 3];
    }
    float bn = pebhh[g * 192 + 128 + j];

    for (int i = tid; i < 2 * 4 * 64; i += 256) (&hsh[0][0][0])[i] = 0.f;
    __syncthreads();

    for (int p = 0; p < T_; p++) {
        float (*cur)[64] = hsh[p & 1];
        float (*nxt)[64] = hsh[(p + 1) & 1];
        for (int s = 0; s < 4; s++) {
            const float4* H4 = reinterpret_cast<const float4*>(cur[s]);
            float4 h0 = H4[kc * 4 + 0], h1 = H4[kc * 4 + 1],
                   h2 = H4[kc * 4 + 2], h3 = H4[kc * 4 + 3];
            float pr = (dot4(wr0, h0) + dot4(wr1, h1)) + (dot4(wr2, h2) + dot4(wr3, h3));
            float pz = (dot4(wz0, h0) + dot4(wz1, h1)) + (dot4(wz2, h2) + dot4(wz3, h3));
            float pn = (dot4(wn0, h0) + dot4(wn1, h1)) + (dot4(wn2, h2) + dot4(wn3, h3));
            pr += __shfl_xor_sync(0xffffffffu, pr, 1); pr += __shfl_xor_sync(0xffffffffu, pr, 2);
            pz += __shfl_xor_sync(0xffffffffu, pz, 1); pz += __shfl_xor_sync(0xffffffffu, pz, 2);
            pn += __shfl_xor_sync(0xffffffffu, pn, 1); pn += __shfl_xor_sync(0xffffffffu, pn, 2);

            int q = q0 + s;
            int nn = q & 127;
            int b = nn >> 3, f = g * 8 + (nn & 7);
            const float* gxb = g_gx2 + ((size_t)q * T_ + p) * GATE3;
            float gr = __ldg(gxb + j);
            float gz = __ldg(gxb + 64 + j);
            float gn = __ldg(gxb + 128 + j);
            float hold = cur[s][j];
            float r = fsigm(gr + pr);
            float z = fsigm(gz + pz);
            float nnv = ftanh(gn + r * (pn + bn));
            float hnew = nnv + z * (hold - nnv);
            if (kc == 0) nxt[s][j] = hnew;
            if (kc == 1) g_rnn[(((size_t)b * T_ + p) * 64 + f) * 64 + j] = hnew;
        }
        __syncthreads();
    }
}

// ================= K6: PE FC + LN + final output =================
// grid (6400), 256 thr.
__global__ __launch_bounds__(256) void k_fc_ln_pe(
    const float* __restrict__ fcW, const float* __restrict__ fcb,
    const float* __restrict__ lng, const float* __restrict__ lnb,
    float* __restrict__ out)
{
    __shared__ float R[64 * 65];
    __shared__ float red[16];
    int n = blockIdx.x;
    int b = n / T_, t = n - b * T_;
    int tid = threadIdx.x;

    for (int idx = tid; idx < 4096; idx += 256) {
        R[(idx >> 6) * 65 + (idx & 63)] = g_rnn[(size_t)n * 4096 + idx];
    }
    __syncthreads();

    int gg = tid >> 5;
    int fq = (tid >> 4) & 1;
    int ot = tid & 15;
    int f0 = gg * 8 + fq * 4;
    int o0 = ot * 4;
    const float* Wg = fcW + (size_t)gg * 4096;
    float acc[4][4];
#pragma unroll
    for (int i = 0; i < 4; i++)
#pragma unroll
        for (int j = 0; j < 4; j++) acc[i][j] = 0.f;
#pragma unroll 4
    for (int k = 0; k < 64; k++) {
        float a[4], w[4];
#pragma unroll
        for (int i = 0; i < 4; i++) a[i] = R[(f0 + i) * 65 + k];
#pragma unroll
        for (int j = 0; j < 4; j++) w[j] = __ldg(&Wg[(o0 + j) * 64 + k]);
#pragma unroll
        for (int i = 0; i < 4; i++)
#pragma unroll
            for (int j = 0; j < 4; j++) acc[i][j] = fmaf(a[i], w[j], acc[i][j]);
    }
    float s1 = 0.f, s2 = 0.f;
#pragma unroll
    for (int i = 0; i < 4; i++)
#pragma unroll
        for (int j = 0; j < 4; j++) {
            float v = acc[i][j] + fcb[gg * 64 + o0 + j];
            acc[i][j] = v;
            s1 += v; s2 += v * v;
        }
    float mu, rs;
    block_stats(s1, s2, red, tid, mu, rs);
#pragma unroll
    for (int i = 0; i < 4; i++) {
        int f = f0 + i;
#pragma unroll
        for (int j = 0; j < 4; j++) {
            int c = o0 + j;
            float yn = (acc[i][j] - mu) * rs * lng[f * 64 + c] + lnb[f * 64 + c];
            float v = g_intra[((size_t)n * 64 + f) * 64 + c] + yn;
            out[(((size_t)(b * 64 + c)) * T_ + t) * 64 + f] = v;
        }
    }
}

// ================= launch =================
extern "C" void kernel_launch(void* const* d_in, const int* in_sizes, int n_in,
                              void* d_out, int out_size) {
    (void)in_sizes; (void)n_in; (void)out_size;
    const float* x         = (const float*)d_in[0];
    const float* iWihf     = (const float*)d_in[1];
    const float* iWhhf     = (const float*)d_in[2];
    const float* ibihf     = (const float*)d_in[3];
    const float* ibhhf     = (const float*)d_in[4];
    const float* iWihb     = (const float*)d_in[5];
    const float* iWhhb     = (const float*)d_in[6];
    const float* ibihb     = (const float*)d_in[7];
    const float* ibhhb     = (const float*)d_in[8];
    const float* ifcW      = (const float*)d_in[9];
    const float* ifcb      = (const float*)d_in[10];
    const float* ilng      = (const float*)d_in[11];
    const float* ilnb      = (const float*)d_in[12];
    const float* peWih     = (const float*)d_in[13];
    const float* peWhh     = (const float*)d_in[14];
    const float* pebih     = (const float*)d_in[15];
    const float* pebhh     = (const float*)d_in[16];
    const float* pefcW     = (const float*)d_in[17];
    const float* pefcb     = (const float*)d_in[18];
    const float* pelng     = (const float*)d_in[19];
    const float* pelnb     = (const float*)d_in[20];

    const int SM1 = (64 * 65 + 192 * 65 + 192) * 4;             // 67,328 B
    const int SM3 = (64 * 129 * 2 + 64 * 65 + 16) * 4;          // 82,752 B
    const int SM4 = (40 * 65 + 192 * 65 + 192) * 4;             // 61,088 B
    cudaFuncSetAttribute(k_gx_intra,    cudaFuncAttributeMaxDynamicSharedMemorySize, SM1);
    cudaFuncSetAttribute(k_fc_ln_intra, cudaFuncAttributeMaxDynamicSharedMemorySize, SM3);
    cudaFuncSetAttribute(k_gx_pe,       cudaFuncAttributeMaxDynamicSharedMemorySize, SM4);

    k_gx_intra<<<dim3(N1, 2), 256, SM1>>>(x, iWihf, ibihf, ibhhf, iWihb, ibihb, ibhhb);
    k_rec_intra<<<dim3(N1 / 16, 2), 256>>>(iWhhf, ibhhf, iWhhb, ibhhb);
    k_fc_ln_intra<<<N1, 256, SM3>>>(x, ifcW, ifcb, ilng, ilnb);
    k_gx_pe<<<NQ * 10, 256, SM4>>>(peWih, pebih, pebhh);
    k_rec_pe<<<NQ / 4, 256>>>(peWhh, pebhh);
    k_fc_ln_pe<<<N1, 256>>>(pefcW, pefcb, pelng, pelnb, (float*)d_out);
}

// round 2
// speedup vs baseline: 1.4368x; 1.4368x over previous
#include <cuda_runtime.h>
#include <cstdint>
#include <cstddef>

#define B_ 16
#define C_ 64
#define T_ 400
#define F_ 64
#define H_ 64
#define G_ 8
#define N1 (B_*T_)       // 6400 intra sequences
#define NQ 1024          // PE sequences total (G * 128)
#define GATE3 192

typedef unsigned long long u64;

// ---------------- scratch (static __device__, no allocation) ----------------
__device__ float g_gx1[(size_t)2*N1*F_*GATE3];   // [dir][n][p][192]
__device__ float g_fb [(size_t)N1*F_*128];       // [n][f][fwd64|bwd64]
__device__ float g_intra[(size_t)N1*F_*C_];      // [n=b*T+t][f][c]
__device__ float g_pein[(size_t)B_*F_*T_*C_];    // [b][f][t][c]
__device__ float g_gx2[(size_t)NQ*T_*GATE3];     // [q][t][192]
__device__ float g_rnn[(size_t)B_*T_*F_*H_];     // [b][t][f][h]

// ---------------- helpers ----------------
__device__ __forceinline__ float fsigm(float x) {
    return __fdividef(1.0f, 1.0f + __expf(-x));
}
__device__ __forceinline__ float ftanh(float x) {
    x = fminf(15.0f, fmaxf(-15.0f, x));
    float e = __expf(2.0f * x);
    return __fdividef(e - 1.0f, e + 1.0f);
}
__device__ __forceinline__ u64 pack2s(float v) {
    u64 r; asm("mov.b64 %0,{%1,%2};" : "=l"(r) : "f"(v), "f"(v)); return r;
}
__device__ __forceinline__ float2 unpack2(u64 v) {
    float2 r; asm("mov.b64 {%0,%1},%2;" : "=f"(r.x), "=f"(r.y) : "l"(v)); return r;
}
__device__ __forceinline__ u64 ffma2(u64 a, u64 b, u64 c) {
    u64 d; asm("fma.rn.f32x2 %0,%1,%2,%3;" : "=l"(d) : "l"(a), "l"(b), "l"(c)); return d;
}

// block-wide mean / rsqrt(var) over 4096 values
__device__ __forceinline__ void block_stats(float s1, float s2, float* red, int tid,
                                            float& mu, float& rs) {
#pragma unroll
    for (int o = 16; o; o >>= 1) {
        s1 += __shfl_xor_sync(0xffffffffu, s1, o);
        s2 += __shfl_xor_sync(0xffffffffu, s2, o);
    }
    if ((tid & 31) == 0) { red[tid >> 5] = s1; red[8 + (tid >> 5)] = s2; }
    __syncthreads();
    float a = 0.f, b = 0.f;
#pragma unroll
    for (int w = 0; w < 8; w++) { a += red[w]; b += red[8 + w]; }
    mu = a * (1.0f / 4096.0f);
    float var = b * (1.0f / 4096.0f) - mu * mu;
    rs = rsqrtf(var + 1e-8f);
}

// ================= K1: intra gx (both directions), FFMA2 =================
// grid (6400, 2), 256 thr.  W transposed in smem: Wt[k][g] (pad 194).
__global__ __launch_bounds__(256) void k_gx_intra(
    const float* __restrict__ x,
    const float* __restrict__ Wf, const float* __restrict__ bihf, const float* __restrict__ bhhf,
    const float* __restrict__ Wb, const float* __restrict__ bihb, const float* __restrict__ bhhb)
{
    extern __shared__ float sm[];
    float* xt = sm;               // [64][65]
    float* Wt = sm + 64 * 65;     // [64][194]
    float* bs = Wt + 64 * 194;    // [192]
    int dir = blockIdx.y;
    int n = blockIdx.x;
    int b = n / T_, t = n - b * T_;
    const float* W   = dir ? Wb   : Wf;
    const float* bih = dir ? bihb : bihf;
    const float* bhh = dir ? bhhb : bhhf;
    int tid = threadIdx.x;

    for (int idx = tid; idx < 4096; idx += 256) {
        int c = idx >> 6, f = idx & 63;
        float v = x[(((size_t)(b * 64 + c)) * T_ + t) * 64 + f];
        int p = dir ? 63 - f : f;
        xt[p * 65 + c] = v;
    }
    for (int idx = tid; idx < 12288; idx += 256) {
        int g = idx >> 6, k = idx & 63;
        Wt[k * 194 + g] = W[idx];
    }
    for (int g = tid; g < 192; g += 256)
        bs[g] = bih[g] + (g < 128 ? bhh[g] : 0.0f);
    __syncthreads();

    int tf = tid & 15, tg = tid >> 4;
    int p0 = tf * 4, g0 = tg * 12;
    u64 acc[4][6];
#pragma unroll
    for (int i = 0; i < 4; i++)
#pragma unroll
        for (int u = 0; u < 6; u++) acc[i][u] = 0ULL;

#pragma unroll 4
    for (int k = 0; k < 64; k++) {
        u64 a[4];
#pragma unroll
        for (int i = 0; i < 4; i++) a[i] = pack2s(xt[(p0 + i) * 65 + k]);
        const u64* wrow = reinterpret_cast<const u64*>(&Wt[k * 194 + g0]);
#pragma unroll
        for (int u = 0; u < 6; u++) {
            u64 w = wrow[u];
#pragma unroll
            for (int i = 0; i < 4; i++) acc[i][u] = ffma2(a[i], w, acc[i][u]);
        }
    }
    float* ob = g_gx1 + (((size_t)dir * N1 + n) * 64) * GATE3;
#pragma unroll
    for (int i = 0; i < 4; i++)
#pragma unroll
        for (int u = 0; u < 6; u++) {
            float2 v = unpack2(acc[i][u]);
            ob[(size_t)(p0 + i) * GATE3 + g0 + 2 * u]     = v.x + bs[g0 + 2 * u];
            ob[(size_t)(p0 + i) * GATE3 + g0 + 2 * u + 1] = v.y + bs[g0 + 2 * u + 1];
        }
}

// ================= K2: intra recurrence, 2 seqs/block, FFMA2 + prefetch =================
// grid (3200, 2), 256 thr = (64 units j) x (4 k-slices kc)
__global__ __launch_bounds__(256) void k_rec_intra(
    const float* __restrict__ Whf, const float* __restrict__ bhhf,
    const float* __restrict__ Whb, const float* __restrict__ bhhb)
{
    __shared__ __align__(16) float hsh[2][2][64];
    int dir = blockIdx.y;
    const float* Wh  = dir ? Whb  : Whf;
    const float* bhh = dir ? bhhb : bhhf;
    int tid = threadIdx.x;
    int j = tid >> 2, kc = tid & 3;

    u64 wr[8], wz[8], wn[8];
#pragma unroll
    for (int m = 0; m < 8; m++) {
        wr[m] = *reinterpret_cast<const u64*>(&Wh[(0 * 64 + j) * 64 + kc * 16 + 2 * m]);
        wz[m] = *reinterpret_cast<const u64*>(&Wh[(1 * 64 + j) * 64 + kc * 16 + 2 * m]);
        wn[m] = *reinterpret_cast<const u64*>(&Wh[(2 * 64 + j) * 64 + kc * 16 + 2 * m]);
    }
    float bn = bhh[128 + j];

    for (int i = tid; i < 2 * 2 * 64; i += 256) (&hsh[0][0][0])[i] = 0.f;
    __syncthreads();

    int n0 = blockIdx.x * 2;
    const float* gxbase = g_gx1 + ((size_t)dir * N1 + n0) * 64 * GATE3;

    float grc[2], gzc[2], gnc[2];
#pragma unroll
    for (int s = 0; s < 2; s++) {
        const float* gxb = gxbase + (size_t)s * 64 * GATE3;
        grc[s] = __ldg(gxb + j);
        gzc[s] = __ldg(gxb + 64 + j);
        gnc[s] = __ldg(gxb + 128 + j);
    }

    for (int p = 0; p < 64; p++) {
        float (*cur)[64] = hsh[p & 1];
        float (*nxt)[64] = hsh[(p + 1) & 1];
        int forig = dir ? 63 - p : p;

        float grn[2], gzn[2], gnn2[2];
        if (p < 63) {
#pragma unroll
            for (int s = 0; s < 2; s++) {
                const float* gxb = gxbase + ((size_t)s * 64 + p + 1) * GATE3;
                grn[s] = __ldg(gxb + j);
                gzn[s] = __ldg(gxb + 64 + j);
                gnn2[s] = __ldg(gxb + 128 + j);
            }
        }

#pragma unroll
        for (int s = 0; s < 2; s++) {
            const u64* H2 = reinterpret_cast<const u64*>(cur[s]) + kc * 8;
            u64 sr = 0ULL, sz = 0ULL, sn = 0ULL;
#pragma unroll
            for (int m = 0; m < 8; m++) {
                u64 hv = H2[m];
                sr = ffma2(wr[m], hv, sr);
                sz = ffma2(wz[m], hv, sz);
                sn = ffma2(wn[m], hv, sn);
            }
            float2 fr = unpack2(sr), fz = unpack2(sz), fn = unpack2(sn);
            float pr = fr.x + fr.y, pz = fz.x + fz.y, pn = fn.x + fn.y;
            pr += __shfl_xor_sync(0xffffffffu, pr, 1); pr += __shfl_xor_sync(0xffffffffu, pr, 2);
            pz += __shfl_xor_sync(0xffffffffu, pz, 1); pz += __shfl_xor_sync(0xffffffffu, pz, 2);
            pn += __shfl_xor_sync(0xffffffffu, pn, 1); pn += __shfl_xor_sync(0xffffffffu, pn, 2);

            float hold = cur[s][j];
            float r = fsigm(grc[s] + pr);
            float z = fsigm(gzc[s] + pz);
            float nn = ftanh(gnc[s] + r * (pn + bn));
            float hnew = nn + z * (hold - nn);
            if (kc == 0) nxt[s][j] = hnew;
            if (kc == 1) g_fb[((size_t)(n0 + s) * 64 + forig) * 128 + dir * 64 + j] = hnew;
        }
#pragma unroll
        for (int s = 0; s < 2; s++) { grc[s] = grn[s]; gzc[s] = gzn[s]; gnc[s] = gnn2[s]; }
        __syncthreads();
    }
}

// ================= K3: intra FC + LN + residual prep, FFMA2 =================
// grid (6400), 256 thr.
__global__ __launch_bounds__(256) void k_fc_ln_intra(
    const float* __restrict__ x,
    const float* __restrict__ fcW, const float* __restrict__ fcb,
    const float* __restrict__ lng, const float* __restrict__ lnb)
{
    extern __shared__ float sm[];
    float* A   = sm;                  // [64][129]
    float* Wt  = A + 64 * 129;        // [128][66]  transposed
    float* X   = Wt + 128 * 66;       // [64][65]
    float* red = X + 64 * 65;         // [16]
    int n = blockIdx.x;
    int b = n / T_, t = n - b * T_;
    int tid = threadIdx.x;

    for (int idx = tid; idx < 64 * 128; idx += 256) {
        int f = idx >> 7, k = idx & 127;
        A[f * 129 + k] = g_fb[(size_t)n * 8192 + idx];
        Wt[k * 66 + f] = fcW[idx];     // fcW[o*128+k] -> Wt[k][o]
    }
    for (int idx = tid; idx < 4096; idx += 256) {
        int c = idx >> 6, f = idx & 63;
        X[f * 65 + c] = x[(((size_t)(b * 64 + c)) * T_ + t) * 64 + f];
    }
    __syncthreads();

    int tf = tid & 15, to = tid >> 4;
    int f0 = tf * 4, o0 = to * 4;
    u64 acc[4][2];
#pragma unroll
    for (int i = 0; i < 4; i++)
#pragma unroll
        for (int u = 0; u < 2; u++) acc[i][u] = 0ULL;
#pragma unroll 4
    for (int k = 0; k < 128; k++) {
        u64 a[4];
#pragma unroll
        for (int i = 0; i < 4; i++) a[i] = pack2s(A[(f0 + i) * 129 + k]);
        const u64* wrow = reinterpret_cast<const u64*>(&Wt[k * 66 + o0]);
#pragma unroll
        for (int u = 0; u < 2; u++) {
            u64 w = wrow[u];
#pragma unroll
            for (int i = 0; i < 4; i++) acc[i][u] = ffma2(a[i], w, acc[i][u]);
        }
    }
    float vacc[4][4];
    float s1 = 0.f, s2 = 0.f;
#pragma unroll
    for (int i = 0; i < 4; i++)
#pragma unroll
        for (int u = 0; u < 2; u++) {
            float2 v = unpack2(acc[i][u]);
            float v0 = v.x + fcb[o0 + 2 * u];
            float v1 = v.y + fcb[o0 + 2 * u + 1];
            vacc[i][2 * u] = v0; vacc[i][2 * u + 1] = v1;
            s1 += v0 + v1; s2 += v0 * v0 + v1 * v1;
        }
    float mu, rs;
    block_stats(s1, s2, red, tid, mu, rs);
#pragma unroll
    for (int i = 0; i < 4; i++) {
        int f = f0 + i;
#pragma unroll
        for (int jj = 0; jj < 4; jj++) {
            int c = o0 + jj;
            float yn = (vacc[i][jj] - mu) * rs * lng[f * 64 + c] + lnb[f * 64 + c];
            g_intra[((size_t)n * 64 + f) * 64 + c] = yn;
            g_pein[(((size_t)(b * 64 + f)) * T_ + t) * 64 + c] = X[f * 65 + c] + yn;
        }
    }
}

// ================= K4: PE gx, FFMA2 =================
// grid (1024*10), 256 thr. 40 t-rows per block.
__global__ __launch_bounds__(256) void k_gx_pe(
    const float* __restrict__ peWih, const float* __restrict__ pebih,
    const float* __restrict__ pebhh)
{
    extern __shared__ float sm[];
    float* xt = sm;              // [40][65]
    float* Wt = sm + 40 * 65;    // [64][194]
    float* bs = Wt + 64 * 194;   // [192]
    int bx = blockIdx.x;
    int q = bx / 10, tc = bx - q * 10;
    int t0 = tc * 40;
    int g = q >> 7, nn = q & 127;
    int b = nn >> 3, f = g * 8 + (nn & 7);
    int tid = threadIdx.x;
    const float* W   = peWih + (size_t)g * 12288;
    const float* bih = pebih + g * 192;
    const float* bhh = pebhh + g * 192;

    for (int idx = tid; idx < 2560; idx += 256) {
        int lt = idx >> 6, c = idx & 63;
        xt[lt * 65 + c] = g_pein[(((size_t)(b * 64 + f)) * T_ + t0 + lt) * 64 + c];
    }
    for (int idx = tid; idx < 12288; idx += 256) {
        int gg = idx >> 6, k = idx & 63;
        Wt[k * 194 + gg] = W[idx];
    }
    for (int gg = tid; gg < 192; gg += 256)
        bs[gg] = bih[gg] + (gg < 128 ? bhh[gg] : 0.0f);
    __syncthreads();

    int tf = tid & 7, tg = tid >> 3;
    int r0 = tf * 5, g0 = tg * 6;
    u64 acc[5][3];
#pragma unroll
    for (int i = 0; i < 5; i++)
#pragma unroll
        for (int u = 0; u < 3; u++) acc[i][u] = 0ULL;
#pragma unroll 4
    for (int k = 0; k < 64; k++) {
        u64 a[5];
#pragma unroll
        for (int i = 0; i < 5; i++) a[i] = pack2s(xt[(r0 + i) * 65 + k]);
        const u64* wrow = reinterpret_cast<const u64*>(&Wt[k * 194 + g0]);
#pragma unroll
        for (int u = 0; u < 3; u++) {
            u64 w = wrow[u];
#pragma unroll
            for (int i = 0; i < 5; i++) acc[i][u] = ffma2(a[i], w, acc[i][u]);
        }
    }
    float* ob = g_gx2 + ((size_t)q * T_ + t0) * GATE3;
#pragma unroll
    for (int i = 0; i < 5; i++)
#pragma unroll
        for (int u = 0; u < 3; u++) {
            float2 v = unpack2(acc[i][u]);
            ob[(size_t)(r0 + i) * GATE3 + g0 + 2 * u]     = v.x + bs[g0 + 2 * u];
            ob[(size_t)(r0 + i) * GATE3 + g0 + 2 * u + 1] = v.y + bs[g0 + 2 * u + 1];
        }
}

// ================= K5: PE recurrence, 1 seq/block, FFMA2 + prefetch =================
// grid (1024), 256 thr.
__global__ __launch_bounds__(256) void k_rec_pe(
    const float* __restrict__ peWhh, const float* __restrict__ pebhh)
{
    __shared__ __align__(16) float hsh[2][64];
    int tid = threadIdx.x;
    int j = tid >> 2, kc = tid & 3;
    int q = blockIdx.x;
    int g = q >> 7;
    const float* Wh = peWhh + (size_t)g * 12288;
    u64 wr[8], wz[8], wn[8];
#pragma unroll
    for (int m = 0; m < 8; m++) {
        wr[m] = *reinterpret_cast<const u64*>(&Wh[(0 * 64 + j) * 64 + kc * 16 + 2 * m]);
        wz[m] = *reinterpret_cast<const u64*>(&Wh[(1 * 64 + j) * 64 + kc * 16 + 2 * m]);
        wn[m] = *reinterpret_cast<const u64*>(&Wh[(2 * 64 + j) * 64 + kc * 16 + 2 * m]);
    }
    float bn = pebhh[g * 192 + 128 + j];

    int nn = q & 127;
    int b = nn >> 3, f = g * 8 + (nn & 7);

    for (int i = tid; i < 2 * 64; i += 256) (&hsh[0][0])[i] = 0.f;
    __syncthreads();

    const float* gxbase = g_gx2 + (size_t)q * T_ * GATE3;
    float grc = __ldg(gxbase + j);
    float gzc = __ldg(gxbase + 64 + j);
    float gnc = __ldg(gxbase + 128 + j);

    for (int p = 0; p < T_; p++) {
        float* cur = hsh[p & 1];
        float* nxt = hsh[(p + 1) & 1];

        float grn = 0.f, gzn = 0.f, gnn2 = 0.f;
        if (p < T_ - 1) {
            const float* gxb = gxbase + (size_t)(p + 1) * GATE3;
            grn = __ldg(gxb + j);
            gzn = __ldg(gxb + 64 + j);
            gnn2 = __ldg(gxb + 128 + j);
        }

        const u64* H2 = reinterpret_cast<const u64*>(cur) + kc * 8;
        u64 sr = 0ULL, sz = 0ULL, sn = 0ULL;
#pragma unroll
        for (int m = 0; m < 8; m++) {
            u64 hv = H2[m];
            sr = ffma2(wr[m], hv, sr);
            sz = ffma2(wz[m], hv, sz);
            sn = ffma2(wn[m], hv, sn);
        }
        float2 fr = unpack2(sr), fz = unpack2(sz), fn = unpack2(sn);
        float pr = fr.x + fr.y, pz = fz.x + fz.y, pn = fn.x + fn.y;
        pr += __shfl_xor_sync(0xffffffffu, pr, 1); pr += __shfl_xor_sync(0xffffffffu, pr, 2);
        pz += __shfl_xor_sync(0xffffffffu, pz, 1); pz += __shfl_xor_sync(0xffffffffu, pz, 2);
        pn += __shfl_xor_sync(0xffffffffu, pn, 1); pn += __shfl_xor_sync(0xffffffffu, pn, 2);

        float hold = cur[j];
        float r = fsigm(grc + pr);
        float z = fsigm(gzc + pz);
        float nnv = ftanh(gnc + r * (pn + bn));
        float hnew = nnv + z * (hold - nnv);
        if (kc == 0) nxt[j] = hnew;
        if (kc == 1) g_rnn[(((size_t)b * T_ + p) * 64 + f) * 64 + j] = hnew;

        grc = grn; gzc = gzn; gnc = gnn2;
        __syncthreads();
    }
}

// ================= K6: PE FC + LN + final output =================
// grid (6400), 256 thr.
__global__ __launch_bounds__(256) void k_fc_ln_pe(
    const float* __restrict__ fcW, const float* __restrict__ fcb,
    const float* __restrict__ lng, const float* __restrict__ lnb,
    float* __restrict__ out)
{
    __shared__ float R[64 * 65];
    __shared__ float red[16];
    int n = blockIdx.x;
    int b = n / T_, t = n - b * T_;
    int tid = threadIdx.x;

    for (int idx = tid; idx < 4096; idx += 256) {
        R[(idx >> 6) * 65 + (idx & 63)] = g_rnn[(size_t)n * 4096 + idx];
    }
    __syncthreads();

    int gg = tid >> 5;
    int fq = (tid >> 4) & 1;
    int ot = tid & 15;
    int f0 = gg * 8 + fq * 4;
    int o0 = ot * 4;
    const float* Wg = fcW + (size_t)gg * 4096;
    float acc[4][4];
#pragma unroll
    for (int i = 0; i < 4; i++)
#pragma unroll
        for (int j = 0; j < 4; j++) acc[i][j] = 0.f;
#pragma unroll 4
    for (int k = 0; k < 64; k++) {
        float a[4], w[4];
#pragma unroll
        for (int i = 0; i < 4; i++) a[i] = R[(f0 + i) * 65 + k];
#pragma unroll
        for (int j = 0; j < 4; j++) w[j] = __ldg(&Wg[(o0 + j) * 64 + k]);
#pragma unroll
        for (int i = 0; i < 4; i++)
#pragma unroll
            for (int j = 0; j < 4; j++) acc[i][j] = fmaf(a[i], w[j], acc[i][j]);
    }
    float s1 = 0.f, s2 = 0.f;
#pragma unroll
    for (int i = 0; i < 4; i++)
#pragma unroll
        for (int j = 0; j < 4; j++) {
            float v = acc[i][j] + fcb[gg * 64 + o0 + j];
            acc[i][j] = v;
            s1 += v; s2 += v * v;
        }
    float mu, rs;
    block_stats(s1, s2, red, tid, mu, rs);
#pragma unroll
    for (int i = 0; i < 4; i++) {
        int f = f0 + i;
#pragma unroll
        for (int j = 0; j < 4; j++) {
            int c = o0 + j;
            float yn = (acc[i][j] - mu) * rs * lng[f * 64 + c] + lnb[f * 64 + c];
            float v = g_intra[((size_t)n * 64 + f) * 64 + c] + yn;
            out[(((size_t)(b * 64 + c)) * T_ + t) * 64 + f] = v;
        }
    }
}

// ================= launch =================
extern "C" void kernel_launch(void* const* d_in, const int* in_sizes, int n_in,
                              void* d_out, int out_size) {
    (void)in_sizes; (void)n_in; (void)out_size;
    const float* x         = (const float*)d_in[0];
    const float* iWihf     = (const float*)d_in[1];
    const float* iWhhf     = (const float*)d_in[2];
    const float* ibihf     = (const float*)d_in[3];
    const float* ibhhf     = (const float*)d_in[4];
    const float* iWihb     = (const float*)d_in[5];
    const float* iWhhb     = (const float*)d_in[6];
    const float* ibihb     = (const float*)d_in[7];
    const float* ibhhb     = (const float*)d_in[8];
    const float* ifcW      = (const float*)d_in[9];
    const float* ifcb      = (const float*)d_in[10];
    const float* ilng      = (const float*)d_in[11];
    const float* ilnb      = (const float*)d_in[12];
    const float* peWih     = (const float*)d_in[13];
    const float* peWhh     = (const float*)d_in[14];
    const float* pebih     = (const float*)d_in[15];
    const float* pebhh     = (const float*)d_in[16];
    const float* pefcW     = (const float*)d_in[17];
    const float* pefcb     = (const float*)d_in[18];
    const float* pelng     = (const float*)d_in[19];
    const float* pelnb     = (const float*)d_in[20];

    const int SM1 = (64 * 65 + 64 * 194 + 192) * 4;                // 67,072 B
    const int SM3 = (64 * 129 + 128 * 66 + 64 * 65 + 16) * 4;      // 83,520 B
    const int SM4 = (40 * 65 + 64 * 194 + 192) * 4;                // 60,832 B
    cudaFuncSetAttribute(k_gx_intra,    cudaFuncAttributeMaxDynamicSharedMemorySize, SM1);
    cudaFuncSetAttribute(k_fc_ln_intra, cudaFuncAttributeMaxDynamicSharedMemorySize, SM3);
    cudaFuncSetAttribute(k_gx_pe,       cudaFuncAttributeMaxDynamicSharedMemorySize, SM4);

    k_gx_intra<<<dim3(N1, 2), 256, SM1>>>(x, iWihf, ibihf, ibhhf, iWihb, ibihb, ibhhb);
    k_rec_intra<<<dim3(N1 / 2, 2), 256>>>(iWhhf, ibhhf, iWhhb, ibhhb);
    k_fc_ln_intra<<<N1, 256, SM3>>>(x, ifcW, ifcb, ilng, ilnb);
    k_gx_pe<<<NQ * 10, 256, SM4>>>(peWih, pebih, pebhh);
    k_rec_pe<<<NQ, 256>>>(peWhh, pebhh);
    k_fc_ln_pe<<<N1, 256>>>(pefcW, pefcb, pelng, pelnb, (float*)d_out);
}